// round 9
// baseline (speedup 1.0000x reference)
#include <cuda_runtime.h>

// ---------------------------------------------------------------------------
// HierarchicalBlockShuffleLayer (R8): 1024 threads, 32 warps, <=64 regs.
//   out[32r+s] = rs*A + (mu*rs)*C2[r,s] + C1[r,s]
//   A = monarch(M) + blockdiag(T); block-diag operands SELECTED in registers
//   from the monarch LDS streams (no extra LDS, no zero-mask reg bloat).
// Warp w: pair p = w&15 (chunks r=p, q=31-p), quad-half = w>>4 (4 quads).
// Tile layout (proven in R6): offset(D) = D*36 + 8*(D>>4).
// ---------------------------------------------------------------------------

typedef unsigned long long u64;

#define THREADS 1024
#define XSTR 36

__device__ __forceinline__ u64 pack2(float a, float b) {
    u64 r; asm("mov.b64 %0, {%1, %2};" : "=l"(r) : "f"(a), "f"(b)); return r;
}
__device__ __forceinline__ u64 dup2(float a) { return pack2(a, a); }
__device__ __forceinline__ void unpack2(float& a, float& b, u64 v) {
    asm("mov.b64 {%0, %1}, %2;" : "=f"(a), "=f"(b) : "l"(v));
}
__device__ __forceinline__ u64 fma2(u64 a, u64 b, u64 c) {
    u64 d; asm("fma.rn.f32x2 %0, %1, %2, %3;" : "=l"(d) : "l"(a), "l"(b), "l"(c)); return d;
}

// smem floats: XP 37376 | Msm 1024 | GS 1024 | SPART 288 (stride 9)
#define XP_FLOATS   37376
#define OFF_MSM     37376
#define OFF_GS      38400
#define OFF_SPART   39424
#define SMEM_FLOATS 39712
#define SMEM_BYTES  (SMEM_FLOATS * 4)
#define CHUNK_STRIDE 1168            // offset(32r) = r * (32*36 + 16)
#define HI_OFF 584                   // offset(32r+16) - offset(32r)

__global__ void __launch_bounds__(THREADS, 1)
hbsl_kernel(const float* __restrict__ x,
            const float* __restrict__ gamma,
            const float* __restrict__ beta,
            const float* __restrict__ bw,
            const float* __restrict__ wrow,
            const float* __restrict__ wcol,
            const float* __restrict__ alphap,
            const float* __restrict__ bias,
            float* __restrict__ out,
            int ntiles) {
    extern __shared__ float XP[];
    float* Msm   = XP + OFF_MSM;        // M[c][lane]
    float* GS    = XP + OFF_GS;         // gamma
    float* SPART = XP + OFF_SPART;      // [quad 8][sub 4][9]  (stride 9)

    const int t = threadIdx.x;
    const int w = t >> 5, l = t & 31;
    const int p = w & 15, hq = w >> 4;  // pair, quad-half
    const int r = p, q = 31 - p;
    const bool pHi = (l < 16);

    // ---- per-block constant build (once; amortized over ~7 tiles) ----
    float C1r, C2r, C1q, C2q;
    float Tr[16], Tq[16];
    {
        float Mreg[32];
        const float alpha = __ldg(alphap);
        {
            float wrl[32];
#pragma unroll
            for (int k = 0; k < 32; k++) wrl[k] = __ldg(wrow + l * 32 + k);
#pragma unroll
            for (int c = 0; c < 32; c++) {
                float acc = 0.f;
#pragma unroll
                for (int k = 0; k < 32; k++) acc += __ldg(wcol + c * 32 + k) * wrl[k];
                Mreg[c] = alpha * acc;
            }
        }
        if (w == 0) {                 // warp 0 publishes M columns to smem
#pragma unroll
            for (int c = 0; c < 32; c++) Msm[c * 32 + l] = Mreg[c];
        }
        for (int i = t; i < 1024; i += THREADS) GS[i] = __ldg(gamma + i);

        const int off = pHi ? 16 : 0;
        const int jf  = pHi ? (15 - l) : (31 - l);
        const int grpR = pHi ? (63 - 2 * r) : (62 - 2 * r);
        const int grpQ = pHi ? (63 - 2 * q) : (62 - 2 * q);
        float Gm = 0.f, Bm = 0.f, Gmq = 0.f, Bmq = 0.f;
#pragma unroll
        for (int c = 0; c < 32; c++) {
            Gm  += __ldg(gamma + 32 * r + c) * Mreg[c];
            Bm  += __ldg(beta  + 32 * r + c) * Mreg[c];
            Gmq += __ldg(gamma + 32 * q + c) * Mreg[c];
            Bmq += __ldg(beta  + 32 * q + c) * Mreg[c];
        }
        float Gb = 0.f, Bb = 0.f, Gbq = 0.f, Bbq = 0.f;
#pragma unroll
        for (int b = 0; b < 16; b++) {
            Tr[b] = __ldg(bw + grpR * 256 + b * 16 + jf);
            Tq[b] = __ldg(bw + grpQ * 256 + b * 16 + jf);
            Gb  += __ldg(gamma + 32 * q + off + b) * Tr[b];
            Bb  += __ldg(beta  + 32 * q + off + b) * Tr[b];
            Gbq += __ldg(gamma + 32 * r + off + b) * Tq[b];
            Bbq += __ldg(beta  + 32 * r + off + b) * Tq[b];
        }
        C1r = Bm + Bb + __ldg(bias + 32 * r + l);
        C2r = -(Gm + Gb);
        C1q = Bmq + Bbq + __ldg(bias + 32 * q + l);
        C2q = -(Gmq + Gbq);
    }
    __syncthreads();

    // loader role: quad la = w&7 (rows 4la..4la+3), sub lh = w>>3 (dims 256lh..)
    const int la = w & 7, lh = w >> 3;

    const float* mr0 = XP + r * CHUNK_STRIDE;
    const float* mr1 = XP + r * CHUNK_STRIDE + HI_OFF;
    const float* mq0 = XP + q * CHUNK_STRIDE;
    const float* mq1 = XP + q * CHUNK_STRIDE + HI_OFF;

    for (int tile = blockIdx.x; tile < ntiles; tile += gridDim.x) {
        const size_t base = (size_t)tile * 32768;   // 32 rows * 1024

        // ---- load: 4 rows x 256 dims per warp; STS.128 transpose ----
        {
            const float* xb = x + base + (size_t)(4 * la) * 1024 + lh * 256;
            const float* gs = GS + lh * 256;
            float s0 = 0.f, s1 = 0.f, s2 = 0.f, s3 = 0.f;
            float p0 = 0.f, p1 = 0.f, p2 = 0.f, p3 = 0.f;
#pragma unroll
            for (int k = 0; k < 8; k++) {
                const int dl = k * 32 + l;
                const int d  = lh * 256 + dl;             // global dim
                const float v0 = __ldg(xb + dl);
                const float v1 = __ldg(xb + 1024 + dl);
                const float v2 = __ldg(xb + 2048 + dl);
                const float v3 = __ldg(xb + 3072 + dl);
                const float g  = gs[dl];
                s0 += v0; p0 += v0 * v0;
                s1 += v1; p1 += v1 * v1;
                s2 += v2; p2 += v2 * v2;
                s3 += v3; p3 += v3 * v3;
                float4 vv = make_float4(v0 * g, v1 * g, v2 * g, v3 * g);
                *(float4*)(XP + d * XSTR + (d >> 4) * 8 + 4 * la) = vv;
            }
#pragma unroll
            for (int o2 = 16; o2 > 0; o2 >>= 1) {
                s0 += __shfl_xor_sync(~0u, s0, o2);
                s1 += __shfl_xor_sync(~0u, s1, o2);
                s2 += __shfl_xor_sync(~0u, s2, o2);
                s3 += __shfl_xor_sync(~0u, s3, o2);
                p0 += __shfl_xor_sync(~0u, p0, o2);
                p1 += __shfl_xor_sync(~0u, p1, o2);
                p2 += __shfl_xor_sync(~0u, p2, o2);
                p3 += __shfl_xor_sync(~0u, p3, o2);
            }
            if (l == 0) {
                float* sp = SPART + (la * 4 + lh) * 9;
                sp[0] = s0; sp[1] = s1; sp[2] = s2; sp[3] = s3;
                sp[4] = p0; sp[5] = p1; sp[6] = p2; sp[7] = p3;
            }
        }
        __syncthreads();

        // ---- stats finalize, redundant per warp: lane l -> row l ----
        float rs_l, murs_l;
        {
            const int qd = l >> 2, rr = l & 3;
            float s = 0.f, pp = 0.f;
#pragma unroll
            for (int sub = 0; sub < 4; sub++) {
                s  += SPART[(qd * 4 + sub) * 9 + rr];
                pp += SPART[(qd * 4 + sub) * 9 + 4 + rr];
            }
            const float mu = s * (1.f / 1024.f);
            rs_l   = rsqrtf(pp * (1.f / 1024.f) - mu * mu + 1e-5f);
            murs_l = mu * rs_l;
        }

        // ---- compute: 4 row-quads per warp; per b: 4 LDS.128 + 2 LDS.32,
        //      block-diag via register SEL of monarch streams, 12 fma2 ----
#pragma unroll 1
        for (int a = 4 * hq; a < 4 * hq + 4; a++) {
            const int go = 4 * a;
            u64 ar0 = 0, ar1 = 0, aq0 = 0, aq1 = 0;
#pragma unroll
            for (int b = 0; b < 16; b++) {
                const ulonglong2 xrL = *(const ulonglong2*)(mr0 + b * XSTR + go);
                const ulonglong2 xrH = *(const ulonglong2*)(mr1 + b * XSTR + go);
                const ulonglong2 xqL = *(const ulonglong2*)(mq0 + b * XSTR + go);
                const ulonglong2 xqH = *(const ulonglong2*)(mq1 + b * XSTR + go);
                const u64 mL = dup2(Msm[b * 32 + l]);          // broadcast-ish 1 wf
                const u64 mH = dup2(Msm[(16 + b) * 32 + l]);
                // monarch
                ar0 = fma2(xrL.x, mL, ar0); ar1 = fma2(xrL.y, mL, ar1);
                ar0 = fma2(xrH.x, mH, ar0); ar1 = fma2(xrH.y, mH, ar1);
                aq0 = fma2(xqL.x, mL, aq0); aq1 = fma2(xqL.y, mL, aq1);
                aq0 = fma2(xqH.x, mH, aq0); aq1 = fma2(xqH.y, mH, aq1);
                // block-diag: operand chosen in registers (ALU SEL, idle pipe)
                const u64 bx0 = pHi ? xqH.x : xqL.x;
                const u64 bx1 = pHi ? xqH.y : xqL.y;
                const u64 cx0 = pHi ? xrH.x : xrL.x;
                const u64 cx1 = pHi ? xrH.y : xrL.y;
                const u64 tr = dup2(Tr[b]);
                const u64 tq = dup2(Tq[b]);
                ar0 = fma2(bx0, tr, ar0); ar1 = fma2(bx1, tr, ar1);
                aq0 = fma2(cx0, tq, aq0); aq1 = fma2(cx1, tq, aq1);
            }
            // epilogue: out = rs*A + murs*C2 + C1 ; rs via SHFL broadcast
            float* orow = out + base + (size_t)go * 1024;
#pragma unroll
            for (int rp = 0; rp < 2; rp++) {
                const int e = go + 2 * rp;
                const u64 RS2 = pack2(__shfl_sync(~0u, rs_l, e),
                                      __shfl_sync(~0u, rs_l, e + 1));
                const u64 MU2 = pack2(__shfl_sync(~0u, murs_l, e),
                                      __shfl_sync(~0u, murs_l, e + 1));
                const u64 vr = fma2(RS2, rp ? ar1 : ar0, fma2(MU2, dup2(C2r), dup2(C1r)));
                const u64 vq = fma2(RS2, rp ? aq1 : aq0, fma2(MU2, dup2(C2q), dup2(C1q)));
                float A, B;
                unpack2(A, B, vr);
                orow[(2 * rp) * 1024 + 32 * r + l]     = A;   // coalesced 128B
                orow[(2 * rp + 1) * 1024 + 32 * r + l] = B;
                unpack2(A, B, vq);
                orow[(2 * rp) * 1024 + 32 * q + l]     = A;
                orow[(2 * rp + 1) * 1024 + 32 * q + l] = B;
            }
        }
        __syncthreads();
    }
}

// ---------------------------------------------------------------------------
extern "C" void kernel_launch(void* const* d_in, const int* in_sizes, int n_in,
                              void* d_out, int out_size) {
    const float* x     = (const float*)d_in[0];
    const float* gamma = (const float*)d_in[1];
    const float* beta  = (const float*)d_in[2];
    const float* bw    = (const float*)d_in[3];
    const float* wrow  = (const float*)d_in[4];
    const float* wcol  = (const float*)d_in[5];
    const float* alpha = (const float*)d_in[6];
    const float* bias  = (const float*)d_in[7];
    float* out = (float*)d_out;

    const int rows = in_sizes[0] / 1024;
    const int ntiles = rows / 32;

    cudaFuncSetAttribute(hbsl_kernel,
                         cudaFuncAttributeMaxDynamicSharedMemorySize, SMEM_BYTES);
    hbsl_kernel<<<148, THREADS, SMEM_BYTES>>>(x, gamma, beta, bw, wrow, wcol,
                                              alpha, bias, out, ntiles);
}

// round 10
// speedup vs baseline: 1.7650x; 1.7650x over previous
#include <cuda_runtime.h>

// ---------------------------------------------------------------------------
// HierarchicalBlockShuffleLayer (R9): R6 core + double-buffered 16-row tiles
// with software-pipelined LDG (issue next tile's loads before computing the
// current one; store them to the other smem buffer after compute).
//   out[32r+s] = rs*A + (mu*rs)*C2[r,s] + C1[r,s]
// Lane = s; warp = chunk pair (w, 31-w). f32x2 packs row pairs.
// Tile layout: offset(D) = D*20 + 8*(D>>4)  (16 rows + cumulative group pad).
// M in smem (lane-indexed, conflict-free) to keep regs ~110 (no spills).
// ---------------------------------------------------------------------------

typedef unsigned long long u64;

#define THREADS 512
#define XSTR 20
#define BUF   20992                  // floats per tile buffer = 656*32
#define CHUNK_STRIDE 656             // offset(32r) - offset(0)
#define HI_OFF 328                   // offset(32r+16) - offset(32r)

__device__ __forceinline__ u64 pack2(float a, float b) {
    u64 r; asm("mov.b64 %0, {%1, %2};" : "=l"(r) : "f"(a), "f"(b)); return r;
}
__device__ __forceinline__ u64 dup2(float a) { return pack2(a, a); }
__device__ __forceinline__ void unpack2(float& a, float& b, u64 v) {
    asm("mov.b64 {%0, %1}, %2;" : "=f"(a), "=f"(b) : "l"(v));
}
__device__ __forceinline__ u64 fma2(u64 a, u64 b, u64 c) {
    u64 d; asm("fma.rn.f32x2 %0, %1, %2, %3;" : "=l"(d) : "l"(a), "l"(b), "l"(c)); return d;
}

// smem floats: XP 2*20992 | Msm 1024 | GS 1024 | SPART 2*144
#define OFF_MSM   41984
#define OFF_GS    43008
#define OFF_SPART 44032
#define SMEM_FLOATS 44320
#define SMEM_BYTES (SMEM_FLOATS * 4)

__global__ void __launch_bounds__(THREADS, 1)
hbsl_kernel(const float* __restrict__ x,
            const float* __restrict__ gamma,
            const float* __restrict__ beta,
            const float* __restrict__ bw,
            const float* __restrict__ wrow,
            const float* __restrict__ wcol,
            const float* __restrict__ alphap,
            const float* __restrict__ bias,
            float* __restrict__ out,
            int ntiles) {
    extern __shared__ float XP[];
    float* Msm   = XP + OFF_MSM;        // M[c][lane]
    float* GS    = XP + OFF_GS;         // gamma
    float* SPART = XP + OFF_SPART;      // [2][16][9]

    const int t = threadIdx.x;
    const int w = t >> 5, l = t & 31;
    const int r = w, q = 31 - w;
    const bool pHi = (l < 16);

    // ---- per-block constant build ----
    float C1r, C2r, C1q, C2q;
    float Tr[16], Tq[16];
    {
        float Mreg[32];
        const float alpha = __ldg(alphap);
        {
            float wrl[32];
#pragma unroll
            for (int k = 0; k < 32; k++) wrl[k] = __ldg(wrow + l * 32 + k);
#pragma unroll
            for (int c = 0; c < 32; c++) {
                float acc = 0.f;
#pragma unroll
                for (int k = 0; k < 32; k++) acc += __ldg(wcol + c * 32 + k) * wrl[k];
                Mreg[c] = alpha * acc;
            }
        }
        if (w == 0) {
#pragma unroll
            for (int c = 0; c < 32; c++) Msm[c * 32 + l] = Mreg[c];
        }
        for (int i = t; i < 1024; i += THREADS) GS[i] = __ldg(gamma + i);

        const int off = pHi ? 16 : 0;
        const int jf  = pHi ? (15 - l) : (31 - l);
        const int grpR = pHi ? (63 - 2 * r) : (62 - 2 * r);
        const int grpQ = pHi ? (63 - 2 * q) : (62 - 2 * q);
        float Gm = 0.f, Bm = 0.f, Gmq = 0.f, Bmq = 0.f;
#pragma unroll
        for (int c = 0; c < 32; c++) {
            Gm  += __ldg(gamma + 32 * r + c) * Mreg[c];
            Bm  += __ldg(beta  + 32 * r + c) * Mreg[c];
            Gmq += __ldg(gamma + 32 * q + c) * Mreg[c];
            Bmq += __ldg(beta  + 32 * q + c) * Mreg[c];
        }
        float Gb = 0.f, Bb = 0.f, Gbq = 0.f, Bbq = 0.f;
#pragma unroll
        for (int b = 0; b < 16; b++) {
            Tr[b] = __ldg(bw + grpR * 256 + b * 16 + jf);
            Tq[b] = __ldg(bw + grpQ * 256 + b * 16 + jf);
            Gb  += __ldg(gamma + 32 * q + off + b) * Tr[b];
            Bb  += __ldg(beta  + 32 * q + off + b) * Tr[b];
            Gbq += __ldg(gamma + 32 * r + off + b) * Tq[b];
            Bbq += __ldg(beta  + 32 * r + off + b) * Tq[b];
        }
        C1r = Bm + Bb + __ldg(bias + 32 * r + l);
        C2r = -(Gm + Gb);
        C1q = Bmq + Bbq + __ldg(bias + 32 * q + l);
        C2q = -(Gmq + Gbq);
    }
    __syncthreads();

    // loader role: quad la = w&3 (rows 4la..4la+3), sub lh = w>>2 (dims 256lh..)
    const int la = w & 3, lh = w >> 2;
    const int row_f = l & 15;                 // stats row for this lane

    // ---- prologue: load first tile into buffer 0 ----
    int tile = blockIdx.x;
    if (tile < ntiles) {
        const float* xb = x + (size_t)tile * 16384 + (size_t)(4 * la) * 1024 + lh * 256;
        float s0 = 0.f, s1 = 0.f, s2 = 0.f, s3 = 0.f;
        float p0 = 0.f, p1 = 0.f, p2 = 0.f, p3 = 0.f;
#pragma unroll
        for (int k = 0; k < 8; k++) {
            const int dl = k * 32 + l;
            const int d  = lh * 256 + dl;
            const float v0 = __ldg(xb + dl);
            const float v1 = __ldg(xb + 1024 + dl);
            const float v2 = __ldg(xb + 2048 + dl);
            const float v3 = __ldg(xb + 3072 + dl);
            const float g  = GS[d];
            s0 += v0; p0 += v0 * v0;
            s1 += v1; p1 += v1 * v1;
            s2 += v2; p2 += v2 * v2;
            s3 += v3; p3 += v3 * v3;
            *(float4*)(XP + d * XSTR + (d >> 4) * 8 + 4 * la) =
                make_float4(v0 * g, v1 * g, v2 * g, v3 * g);
        }
#pragma unroll
        for (int o2 = 16; o2 > 0; o2 >>= 1) {
            s0 += __shfl_xor_sync(~0u, s0, o2);
            s1 += __shfl_xor_sync(~0u, s1, o2);
            s2 += __shfl_xor_sync(~0u, s2, o2);
            s3 += __shfl_xor_sync(~0u, s3, o2);
            p0 += __shfl_xor_sync(~0u, p0, o2);
            p1 += __shfl_xor_sync(~0u, p1, o2);
            p2 += __shfl_xor_sync(~0u, p2, o2);
            p3 += __shfl_xor_sync(~0u, p3, o2);
        }
        if (l == 0) {
            float* sp = SPART + (la * 4 + lh) * 9;
            sp[0] = s0; sp[1] = s1; sp[2] = s2; sp[3] = s3;
            sp[4] = p0; sp[5] = p1; sp[6] = p2; sp[7] = p3;
        }
    }
    __syncthreads();

    // ---- main pipelined loop ----
    int cb = 0;
    for (; tile < ntiles; tile += gridDim.x, cb ^= 1) {
        const int tn = tile + gridDim.x;
        const bool hasnext = tn < ntiles;

        // 1. issue next tile's LDG early (latency hidden under compute)
        float vl[32];
        if (hasnext) {
            const float* xb = x + (size_t)tn * 16384 + (size_t)(4 * la) * 1024 + lh * 256;
#pragma unroll
            for (int k = 0; k < 8; k++) {
                const int dl = k * 32 + l;
                vl[4 * k + 0] = __ldg(xb + dl);
                vl[4 * k + 1] = __ldg(xb + 1024 + dl);
                vl[4 * k + 2] = __ldg(xb + 2048 + dl);
                vl[4 * k + 3] = __ldg(xb + 3072 + dl);
            }
        }

        // 2. finalize stats for current buffer: lane -> row (l & 15)
        float rs_l, murs_l;
        {
            const float* sp = SPART + cb * 144;
            const int qd = row_f >> 2, rr = row_f & 3;
            float s = 0.f, pp = 0.f;
#pragma unroll
            for (int sub = 0; sub < 4; sub++) {
                s  += sp[(qd * 4 + sub) * 9 + rr];
                pp += sp[(qd * 4 + sub) * 9 + 4 + rr];
            }
            const float mu = s * (1.f / 1024.f);
            rs_l   = rsqrtf(pp * (1.f / 1024.f) - mu * mu + 1e-5f);
            murs_l = mu * rs_l;
        }

        // 3. compute current buffer (4 row-quads) + store out
        {
            const float* XPc = XP + cb * BUF;
            const float* mr0 = XPc + r * CHUNK_STRIDE;
            const float* mr1 = mr0 + HI_OFF;
            const float* mq0 = XPc + q * CHUNK_STRIDE;
            const float* mq1 = mq0 + HI_OFF;
            const float* bR  = pHi ? mq1 : mq0;
            const float* bQ  = pHi ? mr1 : mr0;
            const size_t base = (size_t)tile * 16384;
#pragma unroll 1
            for (int a = 0; a < 4; a++) {
                const int go = 4 * a;
                u64 ar0 = 0, ar1 = 0, aq0 = 0, aq1 = 0;
#pragma unroll
                for (int b = 0; b < 16; b++) {
                    const ulonglong2 xrL = *(const ulonglong2*)(mr0 + b * XSTR + go);
                    const ulonglong2 xrH = *(const ulonglong2*)(mr1 + b * XSTR + go);
                    const ulonglong2 xqL = *(const ulonglong2*)(mq0 + b * XSTR + go);
                    const ulonglong2 xqH = *(const ulonglong2*)(mq1 + b * XSTR + go);
                    const u64 mL = dup2(Msm[b * 32 + l]);
                    const u64 mH = dup2(Msm[(16 + b) * 32 + l]);
                    ar0 = fma2(xrL.x, mL, ar0); ar1 = fma2(xrL.y, mL, ar1);
                    ar0 = fma2(xrH.x, mH, ar0); ar1 = fma2(xrH.y, mH, ar1);
                    aq0 = fma2(xqL.x, mL, aq0); aq1 = fma2(xqL.y, mL, aq1);
                    aq0 = fma2(xqH.x, mH, aq0); aq1 = fma2(xqH.y, mH, aq1);
                    const ulonglong2 bx = *(const ulonglong2*)(bR + b * XSTR + go);
                    const ulonglong2 cx = *(const ulonglong2*)(bQ + b * XSTR + go);
                    const u64 tr = dup2(Tr[b]);
                    const u64 tq = dup2(Tq[b]);
                    ar0 = fma2(bx.x, tr, ar0); ar1 = fma2(bx.y, tr, ar1);
                    aq0 = fma2(cx.x, tq, aq0); aq1 = fma2(cx.y, tq, aq1);
                }
                float* orow = out + base + (size_t)go * 1024;
#pragma unroll
                for (int rp = 0; rp < 2; rp++) {
                    const int e = go + 2 * rp;
                    const u64 RS2 = pack2(__shfl_sync(~0u, rs_l, e),
                                          __shfl_sync(~0u, rs_l, e + 1));
                    const u64 MU2 = pack2(__shfl_sync(~0u, murs_l, e),
                                          __shfl_sync(~0u, murs_l, e + 1));
                    const u64 vr = fma2(RS2, rp ? ar1 : ar0, fma2(MU2, dup2(C2r), dup2(C1r)));
                    const u64 vq = fma2(RS2, rp ? aq1 : aq0, fma2(MU2, dup2(C2q), dup2(C1q)));
                    float A, B;
                    unpack2(A, B, vr);
                    orow[(2 * rp) * 1024 + 32 * r + l]     = A;
                    orow[(2 * rp + 1) * 1024 + 32 * r + l] = B;
                    unpack2(A, B, vq);
                    orow[(2 * rp) * 1024 + 32 * q + l]     = A;
                    orow[(2 * rp + 1) * 1024 + 32 * q + l] = B;
                }
            }
        }

        // 4. stage the (now arrived) next tile into the other buffer
        if (hasnext) {
            float* XPn = XP + (cb ^ 1) * BUF;
            float s0 = 0.f, s1 = 0.f, s2 = 0.f, s3 = 0.f;
            float p0 = 0.f, p1 = 0.f, p2 = 0.f, p3 = 0.f;
#pragma unroll
            for (int k = 0; k < 8; k++) {
                const int dl = k * 32 + l;
                const int d  = lh * 256 + dl;
                const float v0 = vl[4 * k + 0];
                const float v1 = vl[4 * k + 1];
                const float v2 = vl[4 * k + 2];
                const float v3 = vl[4 * k + 3];
                const float g  = GS[d];
                s0 += v0; p0 += v0 * v0;
                s1 += v1; p1 += v1 * v1;
                s2 += v2; p2 += v2 * v2;
                s3 += v3; p3 += v3 * v3;
                *(float4*)(XPn + d * XSTR + (d >> 4) * 8 + 4 * la) =
                    make_float4(v0 * g, v1 * g, v2 * g, v3 * g);
            }
#pragma unroll
            for (int o2 = 16; o2 > 0; o2 >>= 1) {
                s0 += __shfl_xor_sync(~0u, s0, o2);
                s1 += __shfl_xor_sync(~0u, s1, o2);
                s2 += __shfl_xor_sync(~0u, s2, o2);
                s3 += __shfl_xor_sync(~0u, s3, o2);
                p0 += __shfl_xor_sync(~0u, p0, o2);
                p1 += __shfl_xor_sync(~0u, p1, o2);
                p2 += __shfl_xor_sync(~0u, p2, o2);
                p3 += __shfl_xor_sync(~0u, p3, o2);
            }
            if (l == 0) {
                float* sp = SPART + (cb ^ 1) * 144 + (la * 4 + lh) * 9;
                sp[0] = s0; sp[1] = s1; sp[2] = s2; sp[3] = s3;
                sp[4] = p0; sp[5] = p1; sp[6] = p2; sp[7] = p3;
            }
        }
        __syncthreads();
    }
}

// ---------------------------------------------------------------------------
extern "C" void kernel_launch(void* const* d_in, const int* in_sizes, int n_in,
                              void* d_out, int out_size) {
    const float* x     = (const float*)d_in[0];
    const float* gamma = (const float*)d_in[1];
    const float* beta  = (const float*)d_in[2];
    const float* bw    = (const float*)d_in[3];
    const float* wrow  = (const float*)d_in[4];
    const float* wcol  = (const float*)d_in[5];
    const float* alpha = (const float*)d_in[6];
    const float* bias  = (const float*)d_in[7];
    float* out = (float*)d_out;

    const int rows = in_sizes[0] / 1024;
    const int ntiles = rows / 16;

    cudaFuncSetAttribute(hbsl_kernel,
                         cudaFuncAttributeMaxDynamicSharedMemorySize, SMEM_BYTES);
    hbsl_kernel<<<148, THREADS, SMEM_BYTES>>>(x, gamma, beta, bw, wrow, wcol,
                                              alpha, bias, out, ntiles);
}